// round 4
// baseline (speedup 1.0000x reference)
#include <cuda_runtime.h>
#include <cuda_fp16.h>

#define BB 2
#define CC 32
#define HH 128
#define WW 416
#define DD 48
#define HW_ (HH*WW)
#define CHW_ (CC*HH*WW)
#define ISCALE 0.05892556509887896f  // 1/sqrt(C*K2) = 1/sqrt(288)

// Emulate the reference's fp16 cast, stored as float32.
__device__ __forceinline__ float h16(float v) {
    return __half2float(__float2half_rn(v));
}

// Scratch for the LR channel only (device globals — allocation is forbidden)
__device__ float g_nli[BB*HW_];     // 1/max(||patch_l||, eps)
__device__ float g_nri[BB*HW_];
__device__ float g_G[BB*DD*HW_];    // G_{2d}[r,u] = dot_c(xl[r,u], xr[r,u-2d])

// ---------------------------------------------------------------------------
// Kernel A: L and R channels, fully self-contained.
// Block = (128-wide tile, h, b). Box sums + patch norms built in static smem.
// ---------------------------------------------------------------------------
#define TJ 175   // columns needed per tile (128 + 47 halo)
#define SJ 176   // padded stride

__global__ __launch_bounds__(128) void cv_LR_direct_kernel(
    const float* __restrict__ xl,
    const float* __restrict__ xm,
    const float* __restrict__ xr,
    float* __restrict__ out)
{
    __shared__ float s_Al[CC*SJ];   // box3x3(xl) at columns u0+j        (22528 B)
    __shared__ float s_Br[CC*SJ];   // box3x3(xr) at columns u0-47+j     (22528 B)
    __shared__ float s_nA[SJ];      // 1/max(||patch_l||,eps) per column
    __shared__ float s_nB[SJ];      // total 46464 B static

    const int t  = threadIdx.x;
    const int u0 = blockIdx.x * 128;
    const int h  = blockIdx.y;
    const int b  = blockIdx.z;
    const int lane = t & 31;

    // Phase 1: box sums + squared-norm partials. i = j*32 + c puts a whole
    // warp on one column j (c = lane) -> warp-shuffle norm reduction.
    for (int i = t; i < ((TJ*CC + 127) & ~127); i += 128) {
        int c = i & 31;
        int j = i >> 5;           // uniform across the warp
        if (j < TJ) {
            int colA = u0 + j;        // Al column
            int colB = u0 - 47 + j;   // Br column
            float boxA = 0.f, sqA = 0.f, boxB = 0.f, sqB = 0.f;
            const float* pl = xl + b*CHW_ + c*HW_;
            const float* pr = xr + b*CHW_ + c*HW_;
            #pragma unroll
            for (int di = -1; di <= 1; di++) {
                int hh = h + di;
                bool okh = (hh >= 0) && (hh < HH);
                int hc = min(max(hh, 0), HH - 1);
                #pragma unroll
                for (int dj = -1; dj <= 1; dj++) {
                    int wa = colA + dj;
                    int wac = min(max(wa, 0), WW - 1);
                    float va = (okh && wa >= 0 && wa < WW)
                                 ? __ldg(pl + hc*WW + wac) : 0.f;
                    boxA += va; sqA += va*va;
                    int wb = colB + dj;
                    int wbc = min(max(wb, 0), WW - 1);
                    float vb = (okh && wb >= 0 && wb < WW)
                                 ? __ldg(pr + hc*WW + wbc) : 0.f;
                    boxB += vb; sqB += vb*vb;
                }
            }
            s_Al[c*SJ + j] = boxA;
            s_Br[c*SJ + j] = boxB;
            #pragma unroll
            for (int o = 16; o > 0; o >>= 1) {
                sqA += __shfl_xor_sync(0xffffffffu, sqA, o);
                sqB += __shfl_xor_sync(0xffffffffu, sqB, o);
            }
            if (lane == 0) {
                s_nA[j] = 1.f / fmaxf(sqrtf(sqA), 1e-3f);
                s_nB[j] = 1.f / fmaxf(sqrtf(sqB), 1e-3f);
            }
        }
    }
    __syncthreads();

    // Phase 2: per-thread fm (channel-normalized xm), then the 48-d dot loop.
    int w = u0 + t;
    if (w >= WW) return;

    float f[CC];
    {
        float ss = 0.f;
        const float* pm = xm + b*CHW_ + h*WW + w;
        #pragma unroll
        for (int c = 0; c < CC; c++) {
            float v = __ldg(pm + c*HW_);
            f[c] = v; ss += v*v;
        }
        float nf = 1.f / fmaxf(sqrtf(ss), 1e-3f);
        nf *= ISCALE;   // fold output scale
        #pragma unroll
        for (int c = 0; c < CC; c++) f[c] *= nf;
    }

    int ob = (b*3)*DD*HW_ + h*WW + w;   // channel-L base at d=0
    #pragma unroll 2
    for (int d = 0; d < DD; d++) {
        float aL = 0.f, aR = 0.f;
        if (w + d < WW) {
            int j = t + d;                 // <= 174
            #pragma unroll
            for (int c = 0; c < CC; c++)
                aL += f[c] * s_Al[c*SJ + j];
            aL *= s_nA[j];
        }
        if (w - d >= 0) {
            int j = t - d + 47;            // in [0,174]
            #pragma unroll
            for (int c = 0; c < CC; c++)
                aR += f[c] * s_Br[c*SJ + j];
            aR *= s_nB[j];
        }
        out[ob + d*HW_]        = h16(fminf(fmaxf(aL, -10.f), 10.f));
        out[ob + (DD + d)*HW_] = h16(fminf(fmaxf(aR, -10.f), 10.f));
    }
}

// ---------------------------------------------------------------------------
// Kernel B: patch norms for the LR channel -> g_nli, g_nri.
// ---------------------------------------------------------------------------
__global__ __launch_bounds__(WW) void cv_norms_kernel(
    const float* __restrict__ xl,
    const float* __restrict__ xr)
{
    __shared__ float s_cs[WW + 2];
    int w = threadIdx.x;
    int h = blockIdx.x;
    int b = blockIdx.y;

    // xl
    {
        float acc = 0.f;
        const float* p = xl + b*CHW_ + h*WW + w;
        #pragma unroll
        for (int di = -1; di <= 1; di++) {
            int hh = h + di;
            if (hh < 0 || hh >= HH) continue;
            const float* q = p + di*WW;
            #pragma unroll
            for (int c = 0; c < CC; c++) {
                float v = __ldg(q + c*HW_);
                acc += v*v;
            }
        }
        if (w == 0) { s_cs[0] = 0.f; s_cs[WW + 1] = 0.f; }
        s_cs[w + 1] = acc;
        __syncthreads();
        float ss = s_cs[w] + s_cs[w + 1] + s_cs[w + 2];
        g_nli[b*HW_ + h*WW + w] = 1.f / fmaxf(sqrtf(ss), 1e-3f);
        __syncthreads();
    }
    // xr
    {
        float acc = 0.f;
        const float* p = xr + b*CHW_ + h*WW + w;
        #pragma unroll
        for (int di = -1; di <= 1; di++) {
            int hh = h + di;
            if (hh < 0 || hh >= HH) continue;
            const float* q = p + di*WW;
            #pragma unroll
            for (int c = 0; c < CC; c++) {
                float v = __ldg(q + c*HW_);
                acc += v*v;
            }
        }
        s_cs[w + 1] = acc;
        __syncthreads();
        float ss = s_cs[w] + s_cs[w + 1] + s_cs[w + 2];
        g_nri[b*HW_ + h*WW + w] = 1.f / fmaxf(sqrtf(ss), 1e-3f);
    }
}

// ---------------------------------------------------------------------------
// Kernel C: G_{2d}[r,u] = dot_c(xl[:,r,u], xr[:,r,u-2d]) (zero if u-2d<0).
// ---------------------------------------------------------------------------
#define T2  208
#define XRW 302   // 94 halo + 208 tile

__global__ __launch_bounds__(T2) void cv_g_kernel(
    const float* __restrict__ xl,
    const float* __restrict__ xr)
{
    __shared__ float s_xr[CC*XRW];   // 38656 B

    int t = threadIdx.x;
    int u0 = blockIdx.x * T2;        // 0 or 208
    int r = blockIdx.y;
    int b = blockIdx.z;
    int lo = u0 - 94;

    int rbase = b*CHW_ + r*WW;
    for (int i = t; i < CC*XRW; i += T2) {
        int c = i / XRW;
        int col = lo + (i % XRW);
        s_xr[i] = (col >= 0) ? __ldg(xr + rbase + c*HW_ + col) : 0.f;
    }
    __syncthreads();

    int u = u0 + t;
    float rl[CC];
    #pragma unroll
    for (int c = 0; c < CC; c++) rl[c] = __ldg(xl + rbase + c*HW_ + u);

    int ob = b*DD*HW_ + r*WW + u;
    #pragma unroll 4
    for (int d = 0; d < DD; d++) {
        int v = u - 2*d;
        float g = 0.f;
        if (v >= 0) {
            int si = v - lo;   // = t + 94 - 2d, in [0, XRW)
            #pragma unroll
            for (int c = 0; c < CC; c++)
                g += rl[c] * s_xr[c*XRW + si];
        }
        g_G[ob + d*HW_] = g;
    }
}

// ---------------------------------------------------------------------------
// Kernel D: LR channel -- 3x3 box over G + normalization.
// ---------------------------------------------------------------------------
__global__ __launch_bounds__(256) void cv_lr_out_kernel(float* __restrict__ out)
{
    int idx = blockIdx.x * 256 + threadIdx.x;
    if (idx >= BB*DD*HW_) return;
    int w = idx % WW;
    int t = idx / WW;
    int h = t % HH; t /= HH;
    int d = t % DD;
    int b = t / DD;

    float val = 0.f;
    if (w >= d && w < WW - d) {
        int u = w + d;
        int gbase = (b*DD + d)*HW_;
        float s = 0.f;
        #pragma unroll
        for (int di = -1; di <= 1; di++) {
            int hh = h + di;
            if (hh < 0 || hh >= HH) continue;
            #pragma unroll
            for (int dj = -1; dj <= 1; dj++) {
                int uu = u + dj;
                if (uu < 0 || uu >= WW) continue;
                s += g_G[gbase + hh*WW + uu];
            }
        }
        float ni = g_nli[b*HW_ + h*WW + u];
        float nr = g_nri[b*HW_ + h*WW + (w - d)];
        val = s * ni * nr * ISCALE;
        val = fminf(fmaxf(val, -10.f), 10.f);
    }
    out[(b*3 + 2)*DD*HW_ + d*HW_ + h*WW + w] = h16(val);
}

// ---------------------------------------------------------------------------
extern "C" void kernel_launch(void* const* d_in, const int* in_sizes, int n_in,
                              void* d_out, int out_size)
{
    const float* xl = (const float*)d_in[0];
    const float* xm = (const float*)d_in[1];
    const float* xr = (const float*)d_in[2];
    float* out = (float*)d_out;

    // L/R channels (channels 0 and 1 of dim-1).
    cv_LR_direct_kernel<<<dim3((WW + 127)/128, HH, BB), 128>>>(xl, xm, xr, out);

    // LR channel (channel 2): norms -> G -> box+normalize.
    cv_norms_kernel<<<dim3(HH, BB), WW>>>(xl, xr);
    cv_g_kernel<<<dim3(WW / T2, HH, BB), T2>>>(xl, xr);
    int n = BB*DD*HW_;
    cv_lr_out_kernel<<<(n + 255)/256, 256>>>(out);
}

// round 5
// speedup vs baseline: 3.3917x; 3.3917x over previous
#include <cuda_runtime.h>
#include <cuda_fp16.h>

#define BB 2
#define CC 32
#define HH 128
#define WW 416
#define DD 48
#define HW_ (HH*WW)
#define CHW_ (CC*HH*WW)
#define ISCALE 0.05892556509887896f  // 1/sqrt(C*K2) = 1/sqrt(288)

// Emulate the reference's fp16 cast, stored as float32.
__device__ __forceinline__ float h16(float v) {
    return __half2float(__float2half_rn(v));
}

// Device-global scratch (allocation forbidden)
__device__ float g_Al[BB*CHW_];     // raw 3x3 box sum of xl (zero-padded)
__device__ float g_Br[BB*CHW_];     // raw 3x3 box sum of xr
__device__ float g_nli[BB*HW_];     // 1/max(||patch_l||, eps)
__device__ float g_nri[BB*HW_];
__device__ float g_G[BB*DD*HW_];    // G_{2d}[r,u] = dot_c(xl[r,u], xr[r,u-2d])

// ---------------------------------------------------------------------------
// Kernel 1: raw 3x3 box sums + patch norms for xl and xr.
// Block = (h, b, img), 416 threads (one per w). Vertical sum in registers,
// horizontal 3-tap via smem. float4 row loads.
// ---------------------------------------------------------------------------
__global__ __launch_bounds__(416) void cv_prep_kernel(
    const float* __restrict__ xl, const float* __restrict__ xr)
{
    __shared__ float s_raw[3*WW];   // 3 input rows of one channel
    __shared__ float s_cs[WW+2];    // vertical sums, zero borders
    __shared__ float s_csq[WW+2];   // vertical sums of squares

    const int w   = threadIdx.x;
    const int h   = blockIdx.x;
    const int b   = blockIdx.y;
    const int img = blockIdx.z;
    const float* x = img ? xr : xl;
    float* gbox = img ? g_Br : g_Al;
    float* gn   = img ? g_nri : g_nli;

    if (w == 0) { s_cs[0] = 0.f; s_cs[WW+1] = 0.f;
                  s_csq[0] = 0.f; s_csq[WW+1] = 0.f; }

    float ssq = 0.f;
    const float* ib = x + b*CHW_;
    float* ob = gbox + b*CHW_ + h*WW + w;

    for (int c = 0; c < CC; c++) {
        // load rows h-1..h+1 of channel c (float4, zero rows OOB)
        for (int i = w; i < 312; i += 416) {
            int r = i / 104, q = i % 104;
            int row = h - 1 + r;
            float4 v = make_float4(0.f, 0.f, 0.f, 0.f);
            if (row >= 0 && row < HH)
                v = *(const float4*)(ib + c*HW_ + row*WW + q*4);
            *(float4*)&s_raw[r*WW + q*4] = v;
        }
        __syncthreads();
        float a0 = s_raw[w], a1 = s_raw[WW + w], a2 = s_raw[2*WW + w];
        s_cs[w+1]  = a0 + a1 + a2;
        s_csq[w+1] = a0*a0 + a1*a1 + a2*a2;
        __syncthreads();
        float box = s_cs[w] + s_cs[w+1] + s_cs[w+2];
        ssq      += s_csq[w] + s_csq[w+1] + s_csq[w+2];
        ob[c*HW_] = box;
        __syncthreads();   // protect smem reuse in next c
    }
    gn[b*HW_ + h*WW + w] = 1.f / fmaxf(sqrtf(ssq), 1e-3f);
}

// ---------------------------------------------------------------------------
// Kernel 2: L and R channels. 128-wide output tiles; box-sum slices + norms
// in static smem (47 KB); fm column held in registers.
// ---------------------------------------------------------------------------
#define SJ 176   // Al window width: [u0, u0+175]
#define BJ 180   // Br window width: [u0-48, u0+131] (16B-aligned start)

__global__ __launch_bounds__(128) void cv_lrcost_kernel(
    const float* __restrict__ xm, float* __restrict__ out)
{
    __shared__ float s_Al[CC*SJ];   // 22528 B
    __shared__ float s_Br[CC*BJ];   // 23040 B
    __shared__ float s_nA[SJ];
    __shared__ float s_nB[BJ];      // total 46992 B

    const int t  = threadIdx.x;
    const int u0 = blockIdx.x * 128;
    const int h  = blockIdx.y;
    const int b  = blockIdx.z;
    const int grow = b*CHW_ + h*WW;

    for (int i = t; i < CC*44; i += 128) {          // Al fill (float4)
        int c = i / 44, q = i % 44;
        int col = u0 + q*4;
        float4 v = make_float4(0.f, 0.f, 0.f, 0.f);
        if (col < WW) v = *(const float4*)(g_Al + grow + c*HW_ + col);
        *(float4*)&s_Al[c*SJ + q*4] = v;
    }
    for (int i = t; i < CC*45; i += 128) {          // Br fill (float4)
        int c = i / 45, q = i % 45;
        int col = u0 - 48 + q*4;
        float4 v = make_float4(0.f, 0.f, 0.f, 0.f);
        if (col >= 0 && col < WW) v = *(const float4*)(g_Br + grow + c*HW_ + col);
        *(float4*)&s_Br[c*BJ + q*4] = v;
    }
    const int nrow = b*HW_ + h*WW;
    for (int j = t; j < SJ; j += 128) {
        int col = u0 + j;
        s_nA[j] = (col < WW) ? g_nli[nrow + col] : 0.f;
    }
    for (int j = t; j < BJ; j += 128) {
        int col = u0 - 48 + j;
        s_nB[j] = (col >= 0 && col < WW) ? g_nri[nrow + col] : 0.f;
    }
    __syncthreads();

    const int w = u0 + t;
    if (w >= WW) return;

    float f[CC];
    {
        float ss = 0.f;
        const float* pm = xm + b*CHW_ + h*WW + w;
        #pragma unroll
        for (int c = 0; c < CC; c++) {
            float v = __ldg(pm + c*HW_);
            f[c] = v; ss += v*v;
        }
        float nf = ISCALE / fmaxf(sqrtf(ss), 1e-3f);
        #pragma unroll
        for (int c = 0; c < CC; c++) f[c] *= nf;
    }

    int ob = (b*3)*DD*HW_ + h*WW + w;   // channel-L base at d=0
    #pragma unroll 2
    for (int d = 0; d < DD; d++) {
        float aL = 0.f, aR = 0.f;
        if (w + d < WW) {
            int j = t + d;                 // [0,175)
            #pragma unroll
            for (int c = 0; c < CC; c++)
                aL += f[c] * s_Al[c*SJ + j];
            aL *= s_nA[j];
        }
        if (w - d >= 0) {
            int j = t - d + 48;            // [1,176)
            #pragma unroll
            for (int c = 0; c < CC; c++)
                aR += f[c] * s_Br[c*BJ + j];
            aR *= s_nB[j];
        }
        out[ob + d*HW_]        = h16(fminf(fmaxf(aL, -10.f), 10.f));
        out[ob + (DD + d)*HW_] = h16(fminf(fmaxf(aR, -10.f), 10.f));
    }
}

// ---------------------------------------------------------------------------
// Kernel 3: G_{2d}[r,u] = dot_c(xl[:,r,u], xr[:,r,u-2d]) (zero if u-2d<0).
// ---------------------------------------------------------------------------
#define T2  208
#define XRW 304   // 96 halo + 208 tile (16B-aligned)

__global__ __launch_bounds__(T2) void cv_g_kernel(
    const float* __restrict__ xl,
    const float* __restrict__ xr)
{
    __shared__ float s_xr[CC*XRW];   // 38912 B

    const int t  = threadIdx.x;
    const int u0 = blockIdx.x * T2;  // 0 or 208
    const int r  = blockIdx.y;
    const int b  = blockIdx.z;
    const int lo = u0 - 96;

    const int rbase = b*CHW_ + r*WW;
    for (int i = t; i < CC*76; i += T2) {     // float4 fill
        int c = i / 76, q = i % 76;
        int col = lo + q*4;                    // max col = u0+204 < WW
        float4 v = make_float4(0.f, 0.f, 0.f, 0.f);
        if (col >= 0) v = *(const float4*)(xr + rbase + c*HW_ + col);
        *(float4*)&s_xr[c*XRW + q*4] = v;
    }
    __syncthreads();

    const int u = u0 + t;
    float rl[CC];
    #pragma unroll
    for (int c = 0; c < CC; c++) rl[c] = __ldg(xl + rbase + c*HW_ + u);

    int ob = b*DD*HW_ + r*WW + u;
    #pragma unroll 4
    for (int d = 0; d < DD; d++) {
        int v = u - 2*d;
        float g = 0.f;
        if (v >= 0) {
            int si = t + 96 - 2*d;   // in [2, 303]
            #pragma unroll
            for (int c = 0; c < CC; c++)
                g += rl[c] * s_xr[c*XRW + si];
        }
        g_G[ob + d*HW_] = g;
    }
}

// ---------------------------------------------------------------------------
// Kernel 4: LR channel -- 3x3 box over G + normalization.
// ---------------------------------------------------------------------------
__global__ __launch_bounds__(256) void cv_lr_out_kernel(float* __restrict__ out)
{
    int idx = blockIdx.x * 256 + threadIdx.x;
    if (idx >= BB*DD*HW_) return;
    int w = idx % WW;
    int t = idx / WW;
    int h = t % HH; t /= HH;
    int d = t % DD;
    int b = t / DD;

    float val = 0.f;
    if (w >= d && w < WW - d) {
        int u = w + d;
        int gbase = (b*DD + d)*HW_;
        float s = 0.f;
        #pragma unroll
        for (int di = -1; di <= 1; di++) {
            int hh = h + di;
            if (hh < 0 || hh >= HH) continue;
            #pragma unroll
            for (int dj = -1; dj <= 1; dj++) {
                int uu = u + dj;
                if (uu < 0 || uu >= WW) continue;
                s += g_G[gbase + hh*WW + uu];
            }
        }
        float ni = g_nli[b*HW_ + h*WW + u];
        float nr = g_nri[b*HW_ + h*WW + (w - d)];
        val = s * ni * nr * ISCALE;
        val = fminf(fmaxf(val, -10.f), 10.f);
    }
    out[(b*3 + 2)*DD*HW_ + d*HW_ + h*WW + w] = h16(val);
}

// ---------------------------------------------------------------------------
extern "C" void kernel_launch(void* const* d_in, const int* in_sizes, int n_in,
                              void* d_out, int out_size)
{
    const float* xl = (const float*)d_in[0];
    const float* xm = (const float*)d_in[1];
    const float* xr = (const float*)d_in[2];
    float* out = (float*)d_out;

    // Box sums + norms once per pixel (both images).
    cv_prep_kernel<<<dim3(HH, BB, 2), 416>>>(xl, xr);

    // L/R channels.
    cv_lrcost_kernel<<<dim3((WW + 127)/128, HH, BB), 128>>>(xm, out);

    // LR channel: G -> box+normalize.
    cv_g_kernel<<<dim3(WW / T2, HH, BB), T2>>>(xl, xr);
    int n = BB*DD*HW_;
    cv_lr_out_kernel<<<(n + 255)/256, 256>>>(out);
}